// round 16
// baseline (speedup 1.0000x reference)
#include <cuda_runtime.h>
#include <cuda_fp16.h>
#include <cstdint>

#define N_NODES 50000
#define E_EDGES 600000
#define IN_DIM  256
#define OUT_DIM 128
#define SCALE   1.8f
#define ALPHA   0.15f
#define ONE_MA  0.85f

// ---------------------------------------------------------------- scratch
__device__ float g_h[(size_t)N_NODES * OUT_DIM];
__device__ float g_z[(size_t)N_NODES * OUT_DIM];
__device__ __align__(16) int g_indeg[N_NODES];
__device__ int   g_off[N_NODES + 1];
__device__ int   g_cursor[N_NODES];
__device__ float g_dinv[N_NODES];
__device__ uint2 g_edge[E_EDGES];          // packed (src, weight)
__device__ __half g_wh[(size_t)OUT_DIM * IN_DIM];   // W in fp16

// ---------------------------------------------------------------- helpers
__device__ __forceinline__ uint32_t smem_u32(const void* p) {
    uint32_t a;
    asm("{ .reg .u64 t; cvta.to.shared.u64 t, %1; cvt.u32.u64 %0, t; }" : "=r"(a) : "l"(p));
    return a;
}
__device__ __forceinline__ void ldsm_x4(uint32_t* r, uint32_t addr) {
    asm volatile("ldmatrix.sync.aligned.m8n8.x4.shared.b16 {%0,%1,%2,%3}, [%4];"
                 : "=r"(r[0]), "=r"(r[1]), "=r"(r[2]), "=r"(r[3]) : "r"(addr));
}
__device__ __forceinline__ void mma_fp16(float* c, const uint32_t* a, const uint32_t* b) {
    asm volatile("mma.sync.aligned.m16n8k16.row.col.f32.f16.f16.f32 "
                 "{%0,%1,%2,%3}, {%4,%5,%6,%7}, {%8,%9}, {%0,%1,%2,%3};"
                 : "+f"(c[0]), "+f"(c[1]), "+f"(c[2]), "+f"(c[3])
                 : "r"(a[0]), "r"(a[1]), "r"(a[2]), "r"(a[3]), "r"(b[0]), "r"(b[1]));
}

// ---------------------------------------------------------------- W fp16 convert
__global__ void k_wconv(const float* __restrict__ W) {
    int i = blockIdx.x * blockDim.x + threadIdx.x;     // pair index
    if (i * 2 >= OUT_DIM * IN_DIM) return;
    float2 v = ((const float2*)W)[i];
    ((__half2*)g_wh)[i] = __floats2half2_rn(v.x, v.y);
}

// ---------------------------------------------------------------- graph-norm build
__global__ void k_deg(const int* __restrict__ ei) {
    int e = (blockIdx.x * blockDim.x + threadIdx.x) * 2;   // E even
    if (e < E_EDGES) {
        int2 c2 = *(const int2*)(ei + E_EDGES + e);
        atomicAdd(&g_indeg[c2.x], 1);
        atomicAdd(&g_indeg[c2.y], 1);
    }
}
// single-block exclusive scan, 4 elems/thread (int4), fused dinv
__global__ void __launch_bounds__(1024) k_scan() {
    __shared__ int wsum[32];
    int lane = threadIdx.x & 31, wid = threadIdx.x >> 5;
    int carry = 0;
    for (int base = 0; base < N_NODES; base += 4096) {
        int i4 = base + threadIdx.x * 4;
        int4 v = make_int4(0, 0, 0, 0);
        if (i4 < N_NODES) v = *(const int4*)(g_indeg + i4);   // N%4==0: full or none
        int vs = v.x + v.y + v.z + v.w;
        int x = vs;
#pragma unroll
        for (int d = 1; d < 32; d <<= 1) {
            int y = __shfl_up_sync(0xFFFFFFFFu, x, d);
            if (lane >= d) x += y;
        }
        if (lane == 31) wsum[wid] = x;
        __syncthreads();
        if (wid == 0) {
            int w = wsum[lane];
#pragma unroll
            for (int d = 1; d < 32; d <<= 1) {
                int y = __shfl_up_sync(0xFFFFFFFFu, w, d);
                if (lane >= d) w += y;
            }
            wsum[lane] = w;
        }
        __syncthreads();
        int excl = x - vs + (wid > 0 ? wsum[wid - 1] : 0) + carry;
        if (i4 < N_NODES) {
            int e0 = excl;
            int e1 = e0 + v.x;
            int e2 = e1 + v.y;
            int e3 = e2 + v.z;
            g_off[i4] = e0;     g_cursor[i4] = e0;
            g_off[i4 + 1] = e1; g_cursor[i4 + 1] = e1;
            g_off[i4 + 2] = e2; g_cursor[i4 + 2] = e2;
            g_off[i4 + 3] = e3; g_cursor[i4 + 3] = e3;
            g_dinv[i4]     = rsqrtf((float)(v.x + 1));
            g_dinv[i4 + 1] = rsqrtf((float)(v.y + 1));
            g_dinv[i4 + 2] = rsqrtf((float)(v.z + 1));
            g_dinv[i4 + 3] = rsqrtf((float)(v.w + 1));
        }
        carry += wsum[31];
        __syncthreads();
    }
    if (threadIdx.x == 0) g_off[N_NODES] = E_EDGES;
}
__global__ void k_place(const int* __restrict__ ei) {
    int e = (blockIdx.x * blockDim.x + threadIdx.x) * 2;   // E even
    if (e < E_EDGES) {
        int2 r2 = *(const int2*)(ei + e);
        int2 c2 = *(const int2*)(ei + E_EDGES + e);
        float dr0 = g_dinv[r2.x], dc0 = g_dinv[c2.x];
        float dr1 = g_dinv[r2.y], dc1 = g_dinv[c2.y];
        int p0 = atomicAdd(&g_cursor[c2.x], 1);
        g_edge[p0] = make_uint2((uint32_t)r2.x, __float_as_uint(dr0 * dc0));
        int p1 = atomicAdd(&g_cursor[c2.y], 1);
        g_edge[p1] = make_uint2((uint32_t)r2.y, __float_as_uint(dr1 * dc1));
    }
}

// ---------------------------------------------------------------- HMMA GEMM
// h = normalize(x @ W^T + b) * SCALE, single fp16 product (X rounded in staging,
// W pre-converted; quadrature error ~2.6e-4 << 1e-3). fp32 accumulate/epilogue.
// 64-row CTA tile (grid 782), 8 warps (32m x 32n), m16n8k16; 3 CTAs/SM.
#define RS 40
__global__ void __launch_bounds__(256, 3) k_gemm_mma(const float* __restrict__ X,
                                                     const float* __restrict__ B) {
    __shared__ __half sA[64 * RS];
    __shared__ __half sB[128 * RS];
    __shared__ float s_bias[OUT_DIM];
    __shared__ float s_ssq[64][4];

    int tid = threadIdx.x, lane = tid & 31, wid = tid >> 5;
    int warp_m = wid & 1;          // 0..1  (32 rows each)
    int warp_n = wid >> 1;         // 0..3  (32 cols each)
    int row0 = blockIdx.x * 64;
    if (tid < OUT_DIM) s_bias[tid] = B[tid];

    uint32_t aA = smem_u32(sA);
    uint32_t aB = smem_u32(sB);

    float c[2][4][4];
#pragma unroll
    for (int mi = 0; mi < 2; mi++)
#pragma unroll
        for (int nj = 0; nj < 4; nj++)
#pragma unroll
            for (int q = 0; q < 4; q++) c[mi][nj][q] = 0.f;

    uint32_t a_row = lane & 15;
    uint32_t a_kh  = lane >> 4;
    uint32_t b_g   = lane >> 3;
    uint32_t b_ln  = lane & 7;

    for (int step = 0; step < 8; step++) {
        int k0 = step * 32;
        // stage X: 64 rows x 32 k (fp32 -> fp16 in-register)
        for (int t = tid; t < 512; t += 256) {
            int r  = t >> 3;
            int cc = (t & 7) << 2;
            int so = r * RS + cc;
            int gr = row0 + r;
            float4 xv = make_float4(0.f, 0.f, 0.f, 0.f);
            if (gr < N_NODES)
                xv = *(const float4*)(X + (size_t)gr * IN_DIM + k0 + cc);
            *(__half2*)(sA + so)     = __floats2half2_rn(xv.x, xv.y);
            *(__half2*)(sA + so + 2) = __floats2half2_rn(xv.z, xv.w);
        }
        // stage W: 128 rows x 32 k (pre-converted fp16, pure 16B copies)
        for (int t = tid; t < 512; t += 256) {
            int r  = t >> 2;
            int cc = (t & 3) << 3;
            *(uint4*)(sB + r * RS + cc) =
                *(const uint4*)(g_wh + (size_t)r * IN_DIM + k0 + cc);
        }
        __syncthreads();

#pragma unroll
        for (int kk = 0; kk < 32; kk += 16) {
            uint32_t ah[2][4];
#pragma unroll
            for (int mi = 0; mi < 2; mi++) {
                uint32_t off = (uint32_t)(warp_m * 32 + mi * 16 + a_row) * (RS * 2)
                             + (kk + a_kh * 8) * 2;
                ldsm_x4(ah[mi], aA + off);
            }
#pragma unroll
            for (int njp = 0; njp < 2; njp++) {
                uint32_t row = (uint32_t)(warp_n * 32 + njp * 16 + (b_g >> 1) * 8 + b_ln);
                uint32_t off = row * (RS * 2) + (kk + (b_g & 1) * 8) * 2;
                uint32_t bh[4];
                ldsm_x4(bh, aB + off);
#pragma unroll
                for (int mi = 0; mi < 2; mi++) {
                    mma_fp16(c[mi][njp * 2],     ah[mi], bh);
                    mma_fp16(c[mi][njp * 2 + 1], ah[mi], bh + 2);
                }
            }
        }
        __syncthreads();
    }

    // epilogue: bias, row L2-norm across four warp_n quarters, scale, store
    int qr = lane >> 2;
    int qc = (lane & 3) * 2;
    float sq[2][2] = {{0.f, 0.f}, {0.f, 0.f}};
#pragma unroll
    for (int mi = 0; mi < 2; mi++)
#pragma unroll
        for (int nj = 0; nj < 4; nj++) {
            int colb = warp_n * 32 + nj * 8 + qc;
            float b0 = s_bias[colb], b1 = s_bias[colb + 1];
            c[mi][nj][0] += b0; c[mi][nj][1] += b1;
            c[mi][nj][2] += b0; c[mi][nj][3] += b1;
            sq[mi][0] += c[mi][nj][0] * c[mi][nj][0] + c[mi][nj][1] * c[mi][nj][1];
            sq[mi][1] += c[mi][nj][2] * c[mi][nj][2] + c[mi][nj][3] * c[mi][nj][3];
        }
#pragma unroll
    for (int mi = 0; mi < 2; mi++)
#pragma unroll
        for (int h = 0; h < 2; h++) {
            float v = sq[mi][h];
            v += __shfl_xor_sync(0xFFFFFFFFu, v, 1);
            v += __shfl_xor_sync(0xFFFFFFFFu, v, 2);
            if ((lane & 3) == 0)
                s_ssq[warp_m * 32 + mi * 16 + h * 8 + qr][warp_n] = v;
        }
    __syncthreads();
#pragma unroll
    for (int mi = 0; mi < 2; mi++)
#pragma unroll
        for (int h = 0; h < 2; h++) {
            int rloc = warp_m * 32 + mi * 16 + h * 8 + qr;
            float tot = s_ssq[rloc][0] + s_ssq[rloc][1] + s_ssq[rloc][2] + s_ssq[rloc][3];
            float s = SCALE / fmaxf(sqrtf(tot), 1e-12f);
            int gr = row0 + rloc;
            if (gr < N_NODES) {
                float* o = g_h + (size_t)gr * OUT_DIM + warp_n * 32 + qc;
#pragma unroll
                for (int nj = 0; nj < 4; nj++) {
                    float2 w2;
                    w2.x = c[mi][nj][h * 2] * s;
                    w2.y = c[mi][nj][h * 2 + 1] * s;
                    *(float2*)(o + nj * 8) = w2;
                }
            }
        }
}

// ---------------------------------------------------------------- gather rounds (measured-best form)
__global__ void __launch_bounds__(256) k_gather1() {
    int n = blockIdx.x * 8 + (threadIdx.x >> 5);
    int lane = threadIdx.x & 31;
    if (n >= N_NODES) return;

    int e0 = g_off[n], e1 = g_off[n + 1];
    float4 acc = make_float4(0.f, 0.f, 0.f, 0.f);
#pragma unroll 2
    for (int e = e0; e < e1; e++) {
        uint2 ed = g_edge[e];
        float w = __uint_as_float(ed.y);
        float4 v = __ldg((const float4*)(g_h + (size_t)ed.x * OUT_DIM) + lane);
        acc.x += w * v.x; acc.y += w * v.y; acc.z += w * v.z; acc.w += w * v.w;
    }
    float dn = g_dinv[n];
    float sc = ONE_MA * dn * dn + ALPHA;
    float4 hh = __ldg((const float4*)(g_h + (size_t)n * OUT_DIM) + lane);
    float4 o;
    o.x = ONE_MA * acc.x + sc * hh.x;
    o.y = ONE_MA * acc.y + sc * hh.y;
    o.z = ONE_MA * acc.z + sc * hh.z;
    o.w = ONE_MA * acc.w + sc * hh.w;
    *((float4*)(g_z + (size_t)n * OUT_DIM) + lane) = o;
}

__global__ void __launch_bounds__(256) k_gather2(float* __restrict__ out) {
    int n = blockIdx.x * 8 + (threadIdx.x >> 5);
    int lane = threadIdx.x & 31;
    if (n >= N_NODES) return;

    int e0 = g_off[n], e1 = g_off[n + 1];
    float4 acc = make_float4(0.f, 0.f, 0.f, 0.f);
#pragma unroll 2
    for (int e = e0; e < e1; e++) {
        uint2 ed = g_edge[e];
        float w = __uint_as_float(ed.y);
        float4 v = __ldg((const float4*)(g_z + (size_t)ed.x * OUT_DIM) + lane);
        acc.x += w * v.x; acc.y += w * v.y; acc.z += w * v.z; acc.w += w * v.w;
    }
    float dn = g_dinv[n];
    float sw = dn * dn;
    float4 cur = __ldg((const float4*)(g_z + (size_t)n * OUT_DIM) + lane);
    float4 hh  = __ldg((const float4*)(g_h + (size_t)n * OUT_DIM) + lane);
    float4 o;
    o.x = ONE_MA * (acc.x + sw * cur.x) + ALPHA * hh.x;
    o.y = ONE_MA * (acc.y + sw * cur.y) + ALPHA * hh.y;
    o.z = ONE_MA * (acc.z + sw * cur.z) + ALPHA * hh.z;
    o.w = ONE_MA * (acc.w + sw * cur.w) + ALPHA * hh.w;
    *((float4*)(out + (size_t)n * OUT_DIM) + lane) = o;
}

// ----------------------------------------------------------------
extern "C" void kernel_launch(void* const* d_in, const int* in_sizes, int n_in,
                              void* d_out, int out_size) {
    const float* x  = (const float*)d_in[0];
    const int*   ei = (const int*)d_in[1];
    const float* W  = (const float*)d_in[2];
    const float* b  = (const float*)d_in[3];
    float* out = (float*)d_out;

    // one-time streams + events + symbol address (host resources only)
    static cudaStream_t s2 = nullptr, s3 = nullptr;
    static cudaEvent_t ev_fork = nullptr, ev_w = nullptr, ev_join = nullptr;
    static void* indeg_ptr = nullptr;
    if (s2 == nullptr) {
        cudaStreamCreateWithFlags(&s2, cudaStreamNonBlocking);
        cudaStreamCreateWithFlags(&s3, cudaStreamNonBlocking);
        cudaEventCreateWithFlags(&ev_fork, cudaEventDisableTiming);
        cudaEventCreateWithFlags(&ev_w, cudaEventDisableTiming);
        cudaEventCreateWithFlags(&ev_join, cudaEventDisableTiming);
        cudaGetSymbolAddress(&indeg_ptr, g_indeg);
    }

    // fork: CSR build on s2, W-convert on s3 (parallel), GEMM on main after ev_w
    cudaEventRecord(ev_fork, 0);
    cudaStreamWaitEvent(s2, ev_fork, 0);
    cudaStreamWaitEvent(s3, ev_fork, 0);

    k_wconv<<<(OUT_DIM * IN_DIM / 2 + 255) / 256, 256, 0, s3>>>(W);
    cudaEventRecord(ev_w, s3);

    cudaMemsetAsync(indeg_ptr, 0, N_NODES * sizeof(int), s2);
    k_deg  <<<(E_EDGES / 2 + 255) / 256, 256, 0, s2>>>(ei);
    k_scan <<<1, 1024, 0, s2>>>();
    k_place<<<(E_EDGES / 2 + 255) / 256, 256, 0, s2>>>(ei);
    cudaEventRecord(ev_join, s2);

    cudaStreamWaitEvent(0, ev_w, 0);
    k_gemm_mma<<<(N_NODES + 63) / 64, 256>>>(x, b);

    // join: gathers need both the GEMM (g_h) and the CSR build
    cudaStreamWaitEvent(0, ev_join, 0);
    k_gather1<<<(N_NODES + 7) / 8, 256>>>();
    k_gather2<<<(N_NODES + 7) / 8, 256>>>(out);
}

// round 17
// speedup vs baseline: 1.1734x; 1.1734x over previous
#include <cuda_runtime.h>
#include <cuda_fp16.h>
#include <cstdint>

#define N_NODES 50000
#define E_EDGES 600000
#define IN_DIM  256
#define OUT_DIM 128
#define SCALE   1.8f
#define ALPHA   0.15f
#define ONE_MA  0.85f

// ---------------------------------------------------------------- scratch
__device__ float g_h[(size_t)N_NODES * OUT_DIM];
__device__ float g_z[(size_t)N_NODES * OUT_DIM];
__device__ __align__(16) int g_indeg[N_NODES];
__device__ int   g_off[N_NODES + 1];
__device__ int   g_cursor[N_NODES];
__device__ float g_dinv[N_NODES];
__device__ uint2 g_edge[E_EDGES];          // packed (src, weight)
__device__ __half g_wh[(size_t)OUT_DIM * IN_DIM];   // W in fp16

// ---------------------------------------------------------------- helpers
__device__ __forceinline__ uint32_t smem_u32(const void* p) {
    uint32_t a;
    asm("{ .reg .u64 t; cvta.to.shared.u64 t, %1; cvt.u32.u64 %0, t; }" : "=r"(a) : "l"(p));
    return a;
}
__device__ __forceinline__ void ldsm_x4(uint32_t* r, uint32_t addr) {
    asm volatile("ldmatrix.sync.aligned.m8n8.x4.shared.b16 {%0,%1,%2,%3}, [%4];"
                 : "=r"(r[0]), "=r"(r[1]), "=r"(r[2]), "=r"(r[3]) : "r"(addr));
}
__device__ __forceinline__ void mma_fp16(float* c, const uint32_t* a, const uint32_t* b) {
    asm volatile("mma.sync.aligned.m16n8k16.row.col.f32.f16.f16.f32 "
                 "{%0,%1,%2,%3}, {%4,%5,%6,%7}, {%8,%9}, {%0,%1,%2,%3};"
                 : "+f"(c[0]), "+f"(c[1]), "+f"(c[2]), "+f"(c[3])
                 : "r"(a[0]), "r"(a[1]), "r"(a[2]), "r"(a[3]), "r"(b[0]), "r"(b[1]));
}

// ---------------------------------------------------------------- W fp16 convert
__global__ void k_wconv(const float* __restrict__ W) {
    int i = blockIdx.x * blockDim.x + threadIdx.x;     // pair index
    if (i * 2 >= OUT_DIM * IN_DIM) return;
    float2 v = ((const float2*)W)[i];
    ((__half2*)g_wh)[i] = __floats2half2_rn(v.x, v.y);
}

// ---------------------------------------------------------------- graph-norm build
__global__ void k_deg(const int* __restrict__ ei) {
    int e = (blockIdx.x * blockDim.x + threadIdx.x) * 2;   // E even
    if (e < E_EDGES) {
        int2 c2 = *(const int2*)(ei + E_EDGES + e);
        atomicAdd(&g_indeg[c2.x], 1);
        atomicAdd(&g_indeg[c2.y], 1);
    }
}
// single-block exclusive scan, 4 elems/thread (int4), fused dinv
__global__ void __launch_bounds__(1024) k_scan() {
    __shared__ int wsum[32];
    int lane = threadIdx.x & 31, wid = threadIdx.x >> 5;
    int carry = 0;
    for (int base = 0; base < N_NODES; base += 4096) {
        int i4 = base + threadIdx.x * 4;
        int4 v = make_int4(0, 0, 0, 0);
        if (i4 < N_NODES) v = *(const int4*)(g_indeg + i4);   // N%4==0: full or none
        int vs = v.x + v.y + v.z + v.w;
        int x = vs;
#pragma unroll
        for (int d = 1; d < 32; d <<= 1) {
            int y = __shfl_up_sync(0xFFFFFFFFu, x, d);
            if (lane >= d) x += y;
        }
        if (lane == 31) wsum[wid] = x;
        __syncthreads();
        if (wid == 0) {
            int w = wsum[lane];
#pragma unroll
            for (int d = 1; d < 32; d <<= 1) {
                int y = __shfl_up_sync(0xFFFFFFFFu, w, d);
                if (lane >= d) w += y;
            }
            wsum[lane] = w;
        }
        __syncthreads();
        int excl = x - vs + (wid > 0 ? wsum[wid - 1] : 0) + carry;
        if (i4 < N_NODES) {
            int e0 = excl;
            int e1 = e0 + v.x;
            int e2 = e1 + v.y;
            int e3 = e2 + v.z;
            g_off[i4] = e0;     g_cursor[i4] = e0;
            g_off[i4 + 1] = e1; g_cursor[i4 + 1] = e1;
            g_off[i4 + 2] = e2; g_cursor[i4 + 2] = e2;
            g_off[i4 + 3] = e3; g_cursor[i4 + 3] = e3;
            g_dinv[i4]     = rsqrtf((float)(v.x + 1));
            g_dinv[i4 + 1] = rsqrtf((float)(v.y + 1));
            g_dinv[i4 + 2] = rsqrtf((float)(v.z + 1));
            g_dinv[i4 + 3] = rsqrtf((float)(v.w + 1));
        }
        carry += wsum[31];
        __syncthreads();
    }
    if (threadIdx.x == 0) g_off[N_NODES] = E_EDGES;
}
__global__ void k_place(const int* __restrict__ ei) {
    int e = (blockIdx.x * blockDim.x + threadIdx.x) * 2;   // E even
    if (e < E_EDGES) {
        int2 r2 = *(const int2*)(ei + e);
        int2 c2 = *(const int2*)(ei + E_EDGES + e);
        float dr0 = g_dinv[r2.x], dc0 = g_dinv[c2.x];
        float dr1 = g_dinv[r2.y], dc1 = g_dinv[c2.y];
        int p0 = atomicAdd(&g_cursor[c2.x], 1);
        g_edge[p0] = make_uint2((uint32_t)r2.x, __float_as_uint(dr0 * dc0));
        int p1 = atomicAdd(&g_cursor[c2.y], 1);
        g_edge[p1] = make_uint2((uint32_t)r2.y, __float_as_uint(dr1 * dc1));
    }
}

// ---------------------------------------------------------------- HMMA GEMM
// h = normalize(x @ W^T + b) * SCALE, single fp16 product.
// K-chunk 64 (4 steps): staging MLP=4, half the __syncthreads of K-chunk 32.
// 64-row CTA tile (grid 782), 8 warps (32m x 32n), m16n8k16; 3 CTAs/SM.
#define RS 72
__global__ void __launch_bounds__(256, 3) k_gemm_mma(const float* __restrict__ X,
                                                     const float* __restrict__ B) {
    __shared__ __half sA[64 * RS];
    __shared__ __half sB[128 * RS];
    __shared__ float s_bias[OUT_DIM];
    __shared__ float s_ssq[64][4];

    int tid = threadIdx.x, lane = tid & 31, wid = tid >> 5;
    int warp_m = wid & 1;          // 0..1  (32 rows each)
    int warp_n = wid >> 1;         // 0..3  (32 cols each)
    int row0 = blockIdx.x * 64;
    if (tid < OUT_DIM) s_bias[tid] = B[tid];

    uint32_t aA = smem_u32(sA);
    uint32_t aB = smem_u32(sB);

    float c[2][4][4];
#pragma unroll
    for (int mi = 0; mi < 2; mi++)
#pragma unroll
        for (int nj = 0; nj < 4; nj++)
#pragma unroll
            for (int q = 0; q < 4; q++) c[mi][nj][q] = 0.f;

    uint32_t a_row = lane & 15;
    uint32_t a_kh  = lane >> 4;
    uint32_t b_g   = lane >> 3;
    uint32_t b_ln  = lane & 7;

    for (int step = 0; step < 4; step++) {
        int k0 = step * 64;
        // stage X: 64 rows x 64 k (fp32 -> fp16); 4 independent float4 LDGs/thread
        float4 xv[4];
#pragma unroll
        for (int i = 0; i < 4; i++) {
            int t = tid + i * 256;             // [0,1024)
            int r  = t >> 4;                   // 16 float4 per 64-col row
            int cc = (t & 15) << 2;
            int gr = row0 + r;
            xv[i] = (gr < N_NODES)
                  ? *(const float4*)(X + (size_t)gr * IN_DIM + k0 + cc)
                  : make_float4(0.f, 0.f, 0.f, 0.f);
        }
#pragma unroll
        for (int i = 0; i < 4; i++) {
            int t = tid + i * 256;
            int r  = t >> 4;
            int cc = (t & 15) << 2;
            int so = r * RS + cc;
            *(__half2*)(sA + so)     = __floats2half2_rn(xv[i].x, xv[i].y);
            *(__half2*)(sA + so + 2) = __floats2half2_rn(xv[i].z, xv[i].w);
        }
        // stage W: 128 rows x 64 k (pre-converted fp16); 4 uint4 copies/thread
#pragma unroll
        for (int i = 0; i < 4; i++) {
            int t = tid + i * 256;             // [0,1024)
            int r  = t >> 3;                   // 8 uint4 per 64-col row
            int cc = (t & 7) << 3;
            *(uint4*)(sB + r * RS + cc) =
                *(const uint4*)(g_wh + (size_t)r * IN_DIM + k0 + cc);
        }
        __syncthreads();

#pragma unroll
        for (int kk = 0; kk < 64; kk += 16) {
            uint32_t ah[2][4];
#pragma unroll
            for (int mi = 0; mi < 2; mi++) {
                uint32_t off = (uint32_t)(warp_m * 32 + mi * 16 + a_row) * (RS * 2)
                             + (kk + a_kh * 8) * 2;
                ldsm_x4(ah[mi], aA + off);
            }
#pragma unroll
            for (int njp = 0; njp < 2; njp++) {
                uint32_t row = (uint32_t)(warp_n * 32 + njp * 16 + (b_g >> 1) * 8 + b_ln);
                uint32_t off = row * (RS * 2) + (kk + (b_g & 1) * 8) * 2;
                uint32_t bh[4];
                ldsm_x4(bh, aB + off);
#pragma unroll
                for (int mi = 0; mi < 2; mi++) {
                    mma_fp16(c[mi][njp * 2],     ah[mi], bh);
                    mma_fp16(c[mi][njp * 2 + 1], ah[mi], bh + 2);
                }
            }
        }
        __syncthreads();
    }

    // epilogue: bias, row L2-norm across four warp_n quarters, scale, store
    int qr = lane >> 2;
    int qc = (lane & 3) * 2;
    float sq[2][2] = {{0.f, 0.f}, {0.f, 0.f}};
#pragma unroll
    for (int mi = 0; mi < 2; mi++)
#pragma unroll
        for (int nj = 0; nj < 4; nj++) {
            int colb = warp_n * 32 + nj * 8 + qc;
            float b0 = s_bias[colb], b1 = s_bias[colb + 1];
            c[mi][nj][0] += b0; c[mi][nj][1] += b1;
            c[mi][nj][2] += b0; c[mi][nj][3] += b1;
            sq[mi][0] += c[mi][nj][0] * c[mi][nj][0] + c[mi][nj][1] * c[mi][nj][1];
            sq[mi][1] += c[mi][nj][2] * c[mi][nj][2] + c[mi][nj][3] * c[mi][nj][3];
        }
#pragma unroll
    for (int mi = 0; mi < 2; mi++)
#pragma unroll
        for (int h = 0; h < 2; h++) {
            float v = sq[mi][h];
            v += __shfl_xor_sync(0xFFFFFFFFu, v, 1);
            v += __shfl_xor_sync(0xFFFFFFFFu, v, 2);
            if ((lane & 3) == 0)
                s_ssq[warp_m * 32 + mi * 16 + h * 8 + qr][warp_n] = v;
        }
    __syncthreads();
#pragma unroll
    for (int mi = 0; mi < 2; mi++)
#pragma unroll
        for (int h = 0; h < 2; h++) {
            int rloc = warp_m * 32 + mi * 16 + h * 8 + qr;
            float tot = s_ssq[rloc][0] + s_ssq[rloc][1] + s_ssq[rloc][2] + s_ssq[rloc][3];
            float s = SCALE / fmaxf(sqrtf(tot), 1e-12f);
            int gr = row0 + rloc;
            if (gr < N_NODES) {
                float* o = g_h + (size_t)gr * OUT_DIM + warp_n * 32 + qc;
#pragma unroll
                for (int nj = 0; nj < 4; nj++) {
                    float2 w2;
                    w2.x = c[mi][nj][h * 2] * s;
                    w2.y = c[mi][nj][h * 2 + 1] * s;
                    *(float2*)(o + nj * 8) = w2;
                }
            }
        }
}

// ---------------------------------------------------------------- gather rounds (measured-best form)
__global__ void __launch_bounds__(256) k_gather1() {
    int n = blockIdx.x * 8 + (threadIdx.x >> 5);
    int lane = threadIdx.x & 31;
    if (n >= N_NODES) return;

    int e0 = g_off[n], e1 = g_off[n + 1];
    float4 acc = make_float4(0.f, 0.f, 0.f, 0.f);
#pragma unroll 2
    for (int e = e0; e < e1; e++) {
        uint2 ed = g_edge[e];
        float w = __uint_as_float(ed.y);
        float4 v = __ldg((const float4*)(g_h + (size_t)ed.x * OUT_DIM) + lane);
        acc.x += w * v.x; acc.y += w * v.y; acc.z += w * v.z; acc.w += w * v.w;
    }
    float dn = g_dinv[n];
    float sc = ONE_MA * dn * dn + ALPHA;
    float4 hh = __ldg((const float4*)(g_h + (size_t)n * OUT_DIM) + lane);
    float4 o;
    o.x = ONE_MA * acc.x + sc * hh.x;
    o.y = ONE_MA * acc.y + sc * hh.y;
    o.z = ONE_MA * acc.z + sc * hh.z;
    o.w = ONE_MA * acc.w + sc * hh.w;
    *((float4*)(g_z + (size_t)n * OUT_DIM) + lane) = o;
}

__global__ void __launch_bounds__(256) k_gather2(float* __restrict__ out) {
    int n = blockIdx.x * 8 + (threadIdx.x >> 5);
    int lane = threadIdx.x & 31;
    if (n >= N_NODES) return;

    int e0 = g_off[n], e1 = g_off[n + 1];
    float4 acc = make_float4(0.f, 0.f, 0.f, 0.f);
#pragma unroll 2
    for (int e = e0; e < e1; e++) {
        uint2 ed = g_edge[e];
        float w = __uint_as_float(ed.y);
        float4 v = __ldg((const float4*)(g_z + (size_t)ed.x * OUT_DIM) + lane);
        acc.x += w * v.x; acc.y += w * v.y; acc.z += w * v.z; acc.w += w * v.w;
    }
    float dn = g_dinv[n];
    float sw = dn * dn;
    float4 cur = __ldg((const float4*)(g_z + (size_t)n * OUT_DIM) + lane);
    float4 hh  = __ldg((const float4*)(g_h + (size_t)n * OUT_DIM) + lane);
    float4 o;
    o.x = ONE_MA * (acc.x + sw * cur.x) + ALPHA * hh.x;
    o.y = ONE_MA * (acc.y + sw * cur.y) + ALPHA * hh.y;
    o.z = ONE_MA * (acc.z + sw * cur.z) + ALPHA * hh.z;
    o.w = ONE_MA * (acc.w + sw * cur.w) + ALPHA * hh.w;
    *((float4*)(out + (size_t)n * OUT_DIM) + lane) = o;
}

// ----------------------------------------------------------------
extern "C" void kernel_launch(void* const* d_in, const int* in_sizes, int n_in,
                              void* d_out, int out_size) {
    const float* x  = (const float*)d_in[0];
    const int*   ei = (const int*)d_in[1];
    const float* W  = (const float*)d_in[2];
    const float* b  = (const float*)d_in[3];
    float* out = (float*)d_out;

    // one-time side-stream + events + symbol address (host resources only)
    static cudaStream_t s2 = nullptr;
    static cudaEvent_t ev_fork = nullptr, ev_join = nullptr;
    static void* indeg_ptr = nullptr;
    if (s2 == nullptr) {
        cudaStreamCreateWithFlags(&s2, cudaStreamNonBlocking);
        cudaEventCreateWithFlags(&ev_fork, cudaEventDisableTiming);
        cudaEventCreateWithFlags(&ev_join, cudaEventDisableTiming);
        cudaGetSymbolAddress(&indeg_ptr, g_indeg);
    }

    // fork: CSR build on s2; W-convert + GEMM on the main (capture) stream (R12/R15 schedule)
    cudaEventRecord(ev_fork, 0);
    cudaStreamWaitEvent(s2, ev_fork, 0);

    cudaMemsetAsync(indeg_ptr, 0, N_NODES * sizeof(int), s2);
    k_deg  <<<(E_EDGES / 2 + 255) / 256, 256, 0, s2>>>(ei);
    k_scan <<<1, 1024, 0, s2>>>();
    k_place<<<(E_EDGES / 2 + 255) / 256, 256, 0, s2>>>(ei);
    cudaEventRecord(ev_join, s2);

    k_wconv<<<(OUT_DIM * IN_DIM / 2 + 255) / 256, 256>>>(W);
    k_gemm_mma<<<(N_NODES + 63) / 64, 256>>>(x, b);

    // join: gathers need both the GEMM (g_h) and the CSR build
    cudaStreamWaitEvent(0, ev_join, 0);
    k_gather1<<<(N_NODES + 7) / 8, 256>>>();
    k_gather2<<<(N_NODES + 7) / 8, 256>>>(out);
}